// round 16
// baseline (speedup 1.0000x reference)
#include <cuda_runtime.h>
#include <cuda_fp16.h>
#include <cstdint>

// ============================================================================
// out[T,D] = X[T,D] @ (W_shared + W_expert)^T + bias
// (reference MoE collapses exactly; see R0 analysis)
// R16: overlap cvt with GEMM via per-k-block ready flags + PDL early trigger.
//      cvt converts columns in 16 k-blocks (flag each); GEMM gates each
//      load_chunk(c) on flag[c]. GEMM mainloop = byte-exact R14 otherwise.
// ============================================================================

#define D_DIM   1024
#define T_DIM   16384
#define BM      128
#define BN      128
#define BK      64
#define NST     3
#define THREADS 256
#define APADH   72                          // halves per row (64 + 8 pad), 144B
#define A_HALVES (BM * APADH)               // 9216
#define B_HALVES (BN * APADH)               // 9216
#define STAGE_HALVES (A_HALVES + B_HALVES)  // 18432
#define SMEM_BYTES (NST * STAGE_HALVES * 2) // 110592

#define NKB      16                         // k-blocks of 64 cols
#define XB_PER_K 256                        // X blocks per k-block
#define WB_PER_K 16                         // W blocks per k-block
#define CVT_PER_K (XB_PER_K + WB_PER_K)     // 272
#define GEMM_GRID ((T_DIM / BM) * (D_DIM / BN))   // 1024

__device__ __half g_Xh[(size_t)T_DIM * D_DIM];   // fp16 X (32MB)
__device__ __half g_Wch[(size_t)D_DIM * D_DIM];  // fp16 (Ws+We) (2MB)
__device__ int    g_cnt[NKB];                    // k-block ready counters
__device__ int    g_done;                        // GEMM CTA completion counter

// ---------------------------------------------------------------- helpers
static __device__ __forceinline__ uint32_t smem_u32(const void* p) {
    uint32_t a;
    asm("{ .reg .u64 t; cvta.to.shared.u64 t, %1; cvt.u32.u64 %0, t; }"
        : "=r"(a) : "l"(p));
    return a;
}

static __device__ __forceinline__ void cp16(uint32_t dst, const void* src) {
    asm volatile("cp.async.cg.shared.global [%0], [%1], 16;" :: "r"(dst), "l"(src));
}

static __device__ __forceinline__ uint32_t h2u(__half2 h) {
    uint32_t u;
    __builtin_memcpy(&u, &h, 4);
    return u;
}

static __device__ __forceinline__ void ldm4(uint32_t* r, uint32_t addr) {
    asm volatile("ldmatrix.sync.aligned.m8n8.x4.shared.b16 {%0,%1,%2,%3}, [%4];"
        : "=r"(r[0]), "=r"(r[1]), "=r"(r[2]), "=r"(r[3]) : "r"(addr));
}

static __device__ __forceinline__ void mma16(float* d, const uint32_t* a, const uint32_t* b) {
    asm volatile(
        "mma.sync.aligned.m16n8k16.row.col.f32.f16.f16.f32 "
        "{%0,%1,%2,%3}, {%4,%5,%6,%7}, {%8,%9}, {%0,%1,%2,%3};"
        : "+f"(d[0]), "+f"(d[1]), "+f"(d[2]), "+f"(d[3])
        : "r"(a[0]), "r"(a[1]), "r"(a[2]), "r"(a[3]), "r"(b[0]), "r"(b[1]));
}

// ---------------------------------------------------------------- cvt
// grid = NKB * CVT_PER_K blocks. Block (kb, sub): sub<256 -> X rows 64*sub,
// cols 64*kb; else -> W rows 64*(sub-256), cols 64*kb. 64x64 f32 per block.
__global__ void cvt_kernel(const float* __restrict__ X,
                           const float* __restrict__ Ws,
                           const float* __restrict__ We)
{
#if __CUDA_ARCH__ >= 900
    if (threadIdx.x == 0) cudaTriggerProgrammaticLaunchCompletion();
#endif
    const int kb  = blockIdx.x / CVT_PER_K;
    const int sub = blockIdx.x % CVT_PER_K;
    const int tid = threadIdx.x;
    const int rin = tid >> 2;                 // row within 64-row block
    const int q   = tid & 3;                  // 16-col quad
    const int col0 = kb * BK + q * 16;

    if (sub < XB_PER_K) {
        const int row = sub * 64 + rin;
        const float* src = X + (size_t)row * D_DIM + col0;
        uint4 o0, o1;
        {
            float4 v0 = *(const float4*)(src);
            float4 v1 = *(const float4*)(src + 4);
            float4 v2 = *(const float4*)(src + 8);
            float4 v3 = *(const float4*)(src + 12);
            o0.x = h2u(__floats2half2_rn(v0.x, v0.y));
            o0.y = h2u(__floats2half2_rn(v0.z, v0.w));
            o0.z = h2u(__floats2half2_rn(v1.x, v1.y));
            o0.w = h2u(__floats2half2_rn(v1.z, v1.w));
            o1.x = h2u(__floats2half2_rn(v2.x, v2.y));
            o1.y = h2u(__floats2half2_rn(v2.z, v2.w));
            o1.z = h2u(__floats2half2_rn(v3.x, v3.y));
            o1.w = h2u(__floats2half2_rn(v3.z, v3.w));
        }
        uint4* dst = (uint4*)(g_Xh + (size_t)row * D_DIM + col0);
        dst[0] = o0;
        dst[1] = o1;
    } else {
        const int row = (sub - XB_PER_K) * 64 + rin;
        const float* sa = Ws + (size_t)row * D_DIM + col0;
        const float* sb = We + (size_t)row * D_DIM + col0;
        uint4 o0, o1;
        {
            float4 a0 = *(const float4*)(sa);
            float4 a1 = *(const float4*)(sa + 4);
            float4 a2 = *(const float4*)(sa + 8);
            float4 a3 = *(const float4*)(sa + 12);
            float4 b0 = *(const float4*)(sb);
            float4 b1 = *(const float4*)(sb + 4);
            float4 b2 = *(const float4*)(sb + 8);
            float4 b3 = *(const float4*)(sb + 12);
            o0.x = h2u(__floats2half2_rn(a0.x + b0.x, a0.y + b0.y));
            o0.y = h2u(__floats2half2_rn(a0.z + b0.z, a0.w + b0.w));
            o0.z = h2u(__floats2half2_rn(a1.x + b1.x, a1.y + b1.y));
            o0.w = h2u(__floats2half2_rn(a1.z + b1.z, a1.w + b1.w));
            o1.x = h2u(__floats2half2_rn(a2.x + b2.x, a2.y + b2.y));
            o1.y = h2u(__floats2half2_rn(a2.z + b2.z, a2.w + b2.w));
            o1.z = h2u(__floats2half2_rn(a3.x + b3.x, a3.y + b3.y));
            o1.w = h2u(__floats2half2_rn(a3.z + b3.z, a3.w + b3.w));
        }
        uint4* dst = (uint4*)(g_Wch + (size_t)row * D_DIM + col0);
        dst[0] = o0;
        dst[1] = o1;
    }

    // publish: all stores visible, then bump this k-block's counter
    __threadfence();
    __syncthreads();
    if (tid == 0) atomicAdd(&g_cnt[kb], 1);
}

// ---------------------------------------------------------------- GEMM
__global__ void __launch_bounds__(THREADS, 2)
moe_gemm_kernel(const float* __restrict__ bias, float* __restrict__ Out)
{
    extern __shared__ __half sm[];
    const int tid  = threadIdx.x;
    const int lane = tid & 31, wid = tid >> 5;
    const int wm = wid >> 2, wn = wid & 3;          // 2 x 4 warps, 64x32 tiles
    const int g = lane >> 2, t = lane & 3;

    // 8 consecutive CTAs share one A (X) tile -> L2 reuse of X
    const int m0 = (blockIdx.x >> 3) * BM;
    const int n0 = (blockIdx.x & 7) * BN;

    const uint32_t sbase = smem_u32(sm);

    // ldmatrix lane-constant offsets
    const int arow = ((lane >> 3) & 1) * 8 + (lane & 7);
    const int akh  = (lane >> 4) * 8;
    const int brow = (lane >> 4) * 8 + (lane & 7);
    const int bkh  = ((lane >> 3) & 1) * 8;

    float acc[4][4][4];
#pragma unroll
    for (int mi = 0; mi < 4; mi++)
#pragma unroll
        for (int ni = 0; ni < 4; ni++)
#pragma unroll
            for (int j = 0; j < 4; j++) acc[mi][ni][j] = 0.0f;

    // gate: wait until k-block c is fully converted
    auto wait_chunk = [&](int c) {
        if (tid == 0) {
            unsigned v;
            do {
                asm volatile("ld.acquire.gpu.global.b32 %0, [%1];"
                             : "=r"(v) : "l"(&g_cnt[c]) : "memory");
            } while (v < CVT_PER_K);
        }
        __syncthreads();
    };

    auto load_chunk = [&](int st, int c) {
        const __half* xb = g_Xh + (size_t)m0 * D_DIM + c * BK;
        const __half* wb = g_Wch + (size_t)n0 * D_DIM + c * BK;
        uint32_t ab = sbase + (st * STAGE_HALVES) * 2;
        uint32_t bb = ab + A_HALVES * 2;
#pragma unroll
        for (int i = 0; i < 4; i++) {   // A: 128 rows x 8 segs of 8 halves
            int idx = tid + i * THREADS;
            int row = idx >> 3, seg = idx & 7;
            cp16(ab + (row * APADH + seg * 8) * 2, xb + (size_t)row * D_DIM + seg * 8);
        }
#pragma unroll
        for (int i = 0; i < 4; i++) {   // B: 128 rows x 8 segs
            int idx = tid + i * THREADS;
            int row = idx >> 3, seg = idx & 7;
            cp16(bb + (row * APADH + seg * 8) * 2, wb + (size_t)row * D_DIM + seg * 8);
        }
    };

    // prologue: chunks 0,1 (gated)
#pragma unroll
    for (int s = 0; s < NST - 1; s++) {
        wait_chunk(s);
        load_chunk(s, s);
        asm volatile("cp.async.commit_group;" ::: "memory");
    }

    const int NCHUNK = D_DIM / BK;                   // 16
    for (int c = 0; c < NCHUNK; c++) {
        const int st = c % NST;
        asm volatile("cp.async.wait_group 1;" ::: "memory");
        __syncthreads();

        const uint32_t aB = sbase + (st * STAGE_HALVES) * 2;
        const uint32_t bB = aB + A_HALVES * 2;

#pragma unroll
        for (int ks = 0; ks < 4; ks++) {             // 4 x k=16 steps
            uint32_t af[4][4];
#pragma unroll
            for (int mi = 0; mi < 4; mi++)
                ldm4(af[mi], aB + (((wm * 64 + mi * 16 + arow) * APADH)
                                   + ks * 16 + akh) * 2);
            uint32_t bf[4][2];
#pragma unroll
            for (int p = 0; p < 2; p++) {            // 2 n-pairs of 16 rows
                uint32_t r4[4];
                ldm4(r4, bB + (((wn * 32 + p * 16 + brow) * APADH)
                               + ks * 16 + bkh) * 2);
                bf[p * 2 + 0][0] = r4[0];  bf[p * 2 + 0][1] = r4[1];
                bf[p * 2 + 1][0] = r4[2];  bf[p * 2 + 1][1] = r4[3];
            }
#pragma unroll
            for (int mi = 0; mi < 4; mi++)
#pragma unroll
                for (int ni = 0; ni < 4; ni++)
                    mma16(acc[mi][ni], af[mi], bf[ni]);
        }

        // refill stage (c+2)%3 (chunk c-1's stage; compute done in all warps)
        int nc = c + NST - 1;
        if (nc < NCHUNK) {
            wait_chunk(nc);
            load_chunk(nc % NST, nc);
        }
        asm volatile("cp.async.commit_group;" ::: "memory");  // uniform count
    }

    // ---- epilogue: add bias, store fp32, coalesced float2
#pragma unroll
    for (int mi = 0; mi < 4; mi++) {
        int row = m0 + wm * 64 + mi * 16 + g;
        float* o0 = Out + (size_t)row * D_DIM;
        float* o1 = o0 + (size_t)8 * D_DIM;
#pragma unroll
        for (int ni = 0; ni < 4; ni++) {
            int col = n0 + wn * 32 + ni * 8 + 2 * t;
            float2 bv = *(const float2*)(bias + col);
            float2 v0, v1;
            v0.x = acc[mi][ni][0] + bv.x;  v0.y = acc[mi][ni][1] + bv.y;
            v1.x = acc[mi][ni][2] + bv.x;  v1.y = acc[mi][ni][3] + bv.y;
            *(float2*)(o0 + col) = v0;
            *(float2*)(o1 + col) = v1;
        }
    }

    // last-finishing CTA resets flags for the next graph replay
    __syncthreads();
    if (tid == 0) {
        __threadfence();
        int old = atomicAdd(&g_done, 1);
        if (old == GEMM_GRID - 1) {
#pragma unroll
            for (int i = 0; i < NKB; i++) g_cnt[i] = 0;
            g_done = 0;
            __threadfence();
        }
    }
}

// ---------------------------------------------------------------- launch
extern "C" void kernel_launch(void* const* d_in, const int* in_sizes, int n_in,
                              void* d_out, int out_size)
{
    const float* x    = (const float*)d_in[0];  // (4,4096,1024)
    const float* Ws   = (const float*)d_in[3];  // (1024,1024)
    const float* We   = (const float*)d_in[4];  // (1024,1024)
    const float* bias = (const float*)d_in[6];  // (1024,)
    float* out = (float*)d_out;

    cudaFuncSetAttribute(moe_gemm_kernel,
                         cudaFuncAttributeMaxDynamicSharedMemorySize, SMEM_BYTES);

    // producer: k-block-ordered cvt (flags g_cnt[kb] as blocks complete)
    cvt_kernel<<<NKB * CVT_PER_K, 256>>>(x, Ws, We);

    // consumer: GEMM with PDL so its CTAs schedule as cvt drains
    cudaLaunchConfig_t cfg = {};
    cfg.gridDim = dim3(GEMM_GRID);
    cfg.blockDim = dim3(THREADS);
    cfg.dynamicSmemBytes = SMEM_BYTES;
    cfg.stream = 0;
    cudaLaunchAttribute attr[1];
    attr[0].id = cudaLaunchAttributeProgrammaticStreamSerialization;
    attr[0].val.programmaticStreamSerializationAllowed = 1;
    cfg.attrs = attr;
    cfg.numAttrs = 1;
    cudaLaunchKernelEx(&cfg, moe_gemm_kernel, bias, out);
}

// round 17
// speedup vs baseline: 1.1597x; 1.1597x over previous
#include <cuda_runtime.h>
#include <cuda_fp16.h>
#include <cstdint>

// ============================================================================
// out[T,D] = X[T,D] @ (W_shared + W_expert)^T + bias
// (reference MoE collapses exactly: round-robin routing, single W_expert,
//  weights normalized to 1 => one 16384x1024x1024 GEMM; see R0 analysis)
// R17 FINAL: byte-exact R14 (best = 117.2us). BK=64 amortizes the per-chunk
//   barrier bubble; BM=BN=128, 2 CTAs/SM, cp.async->smem, ldmatrix.x4,
//   mma.sync m16n8k16 fp16 (mantissa == tf32 => rel_err 2.9e-4).
//   Falsified alternatives: R7 reg-pipelining, R8 small tiles, R9/R12 fused
//   A-conversion, R15 PDL, R16 flag-gated overlap.
// ============================================================================

#define D_DIM   1024
#define T_DIM   16384
#define BM      128
#define BN      128
#define BK      64
#define NST     3
#define THREADS 256
#define APADH   72                          // halves per row (64 + 8 pad), 144B
#define A_HALVES (BM * APADH)               // 9216
#define B_HALVES (BN * APADH)               // 9216
#define STAGE_HALVES (A_HALVES + B_HALVES)  // 18432
#define SMEM_BYTES (NST * STAGE_HALVES * 2) // 110592

#define XBLOCKS 8192                        // X: 16M elems / (8/thread * 256)

__device__ __half g_Xh[(size_t)T_DIM * D_DIM];   // fp16 X (32MB)
__device__ __half g_Wch[(size_t)D_DIM * D_DIM];  // fp16 (Ws+We) (2MB)

// ---------------------------------------------------------------- helpers
static __device__ __forceinline__ uint32_t smem_u32(const void* p) {
    uint32_t a;
    asm("{ .reg .u64 t; cvta.to.shared.u64 t, %1; cvt.u32.u64 %0, t; }"
        : "=r"(a) : "l"(p));
    return a;
}

static __device__ __forceinline__ void cp16(uint32_t dst, const void* src) {
    asm volatile("cp.async.cg.shared.global [%0], [%1], 16;" :: "r"(dst), "l"(src));
}

static __device__ __forceinline__ uint32_t h2u(__half2 h) {
    uint32_t u;
    __builtin_memcpy(&u, &h, 4);
    return u;
}

static __device__ __forceinline__ void ldm4(uint32_t* r, uint32_t addr) {
    asm volatile("ldmatrix.sync.aligned.m8n8.x4.shared.b16 {%0,%1,%2,%3}, [%4];"
        : "=r"(r[0]), "=r"(r[1]), "=r"(r[2]), "=r"(r[3]) : "r"(addr));
}

static __device__ __forceinline__ void mma16(float* d, const uint32_t* a, const uint32_t* b) {
    asm volatile(
        "mma.sync.aligned.m16n8k16.row.col.f32.f16.f16.f32 "
        "{%0,%1,%2,%3}, {%4,%5,%6,%7}, {%8,%9}, {%0,%1,%2,%3};"
        : "+f"(d[0]), "+f"(d[1]), "+f"(d[2]), "+f"(d[3])
        : "r"(a[0]), "r"(a[1]), "r"(a[2]), "r"(a[3]), "r"(b[0]), "r"(b[1]));
}

// ---------------------------------------------------------------- pre-pass
// blocks [0, XBLOCKS): X -> fp16, 8 elems/thread, one 16B store.
// blocks [XBLOCKS, XBLOCKS+512): Wc = fp16(Ws + We), 8 elems/thread.
__global__ void cvt_kernel(const float* __restrict__ X,
                           const float* __restrict__ Ws,
                           const float* __restrict__ We)
{
    if (blockIdx.x < XBLOCKS) {
        size_t i = (size_t)blockIdx.x * 256 + threadIdx.x;   // uint4 index
        float4 v0 = ((const float4*)X)[2 * i];
        float4 v1 = ((const float4*)X)[2 * i + 1];
        uint4 o;
        o.x = h2u(__floats2half2_rn(v0.x, v0.y));
        o.y = h2u(__floats2half2_rn(v0.z, v0.w));
        o.z = h2u(__floats2half2_rn(v1.x, v1.y));
        o.w = h2u(__floats2half2_rn(v1.z, v1.w));
        ((uint4*)g_Xh)[i] = o;
    } else {
        size_t i = (size_t)(blockIdx.x - XBLOCKS) * 256 + threadIdx.x;
        float4 a0 = ((const float4*)Ws)[2 * i];
        float4 a1 = ((const float4*)Ws)[2 * i + 1];
        float4 b0 = ((const float4*)We)[2 * i];
        float4 b1 = ((const float4*)We)[2 * i + 1];
        uint4 o;
        o.x = h2u(__floats2half2_rn(a0.x + b0.x, a0.y + b0.y));
        o.y = h2u(__floats2half2_rn(a0.z + b0.z, a0.w + b0.w));
        o.z = h2u(__floats2half2_rn(a1.x + b1.x, a1.y + b1.y));
        o.w = h2u(__floats2half2_rn(a1.z + b1.z, a1.w + b1.w));
        ((uint4*)g_Wch)[i] = o;
    }
}

// ---------------------------------------------------------------- GEMM
__global__ void __launch_bounds__(THREADS, 2)
moe_gemm_kernel(const float* __restrict__ bias, float* __restrict__ Out)
{
    extern __shared__ __half sm[];
    const int tid  = threadIdx.x;
    const int lane = tid & 31, wid = tid >> 5;
    const int wm = wid >> 2, wn = wid & 3;          // 2 x 4 warps, 64x32 tiles
    const int g = lane >> 2, t = lane & 3;

    // 8 consecutive CTAs share one A (X) tile -> L2 reuse of X
    const int m0 = (blockIdx.x >> 3) * BM;
    const int n0 = (blockIdx.x & 7) * BN;

    const uint32_t sbase = smem_u32(sm);

    // ldmatrix lane-constant offsets
    const int arow = ((lane >> 3) & 1) * 8 + (lane & 7);
    const int akh  = (lane >> 4) * 8;
    const int brow = (lane >> 4) * 8 + (lane & 7);
    const int bkh  = ((lane >> 3) & 1) * 8;

    float acc[4][4][4];
#pragma unroll
    for (int mi = 0; mi < 4; mi++)
#pragma unroll
        for (int ni = 0; ni < 4; ni++)
#pragma unroll
            for (int j = 0; j < 4; j++) acc[mi][ni][j] = 0.0f;

    auto load_chunk = [&](int st, int c) {
        const __half* xb = g_Xh + (size_t)m0 * D_DIM + c * BK;
        const __half* wb = g_Wch + (size_t)n0 * D_DIM + c * BK;
        uint32_t ab = sbase + (st * STAGE_HALVES) * 2;
        uint32_t bb = ab + A_HALVES * 2;
#pragma unroll
        for (int i = 0; i < 4; i++) {   // A: 128 rows x 8 segs of 8 halves
            int idx = tid + i * THREADS;
            int row = idx >> 3, seg = idx & 7;
            cp16(ab + (row * APADH + seg * 8) * 2, xb + (size_t)row * D_DIM + seg * 8);
        }
#pragma unroll
        for (int i = 0; i < 4; i++) {   // B: 128 rows x 8 segs
            int idx = tid + i * THREADS;
            int row = idx >> 3, seg = idx & 7;
            cp16(bb + (row * APADH + seg * 8) * 2, wb + (size_t)row * D_DIM + seg * 8);
        }
    };

    // prologue: chunks 0,1
#pragma unroll
    for (int s = 0; s < NST - 1; s++) {
        load_chunk(s, s);
        asm volatile("cp.async.commit_group;" ::: "memory");
    }

    const int NCHUNK = D_DIM / BK;                   // 16
    for (int c = 0; c < NCHUNK; c++) {
        const int st = c % NST;
        asm volatile("cp.async.wait_group 1;" ::: "memory");
        __syncthreads();

        const uint32_t aB = sbase + (st * STAGE_HALVES) * 2;
        const uint32_t bB = aB + A_HALVES * 2;

#pragma unroll
        for (int ks = 0; ks < 4; ks++) {             // 4 x k=16 steps
            uint32_t af[4][4];
#pragma unroll
            for (int mi = 0; mi < 4; mi++)
                ldm4(af[mi], aB + (((wm * 64 + mi * 16 + arow) * APADH)
                                   + ks * 16 + akh) * 2);
            uint32_t bf[4][2];
#pragma unroll
            for (int p = 0; p < 2; p++) {            // 2 n-pairs of 16 rows
                uint32_t r4[4];
                ldm4(r4, bB + (((wn * 32 + p * 16 + brow) * APADH)
                               + ks * 16 + bkh) * 2);
                bf[p * 2 + 0][0] = r4[0];  bf[p * 2 + 0][1] = r4[1];
                bf[p * 2 + 1][0] = r4[2];  bf[p * 2 + 1][1] = r4[3];
            }
#pragma unroll
            for (int mi = 0; mi < 4; mi++)
#pragma unroll
                for (int ni = 0; ni < 4; ni++)
                    mma16(acc[mi][ni], af[mi], bf[ni]);
        }

        // refill stage (c+2)%3 (chunk c-1's stage; compute done in all warps)
        int nc = c + NST - 1;
        if (nc < NCHUNK) load_chunk(nc % NST, nc);
        asm volatile("cp.async.commit_group;" ::: "memory");  // uniform count
    }

    // ---- epilogue: add bias, store fp32, coalesced float2
#pragma unroll
    for (int mi = 0; mi < 4; mi++) {
        int row = m0 + wm * 64 + mi * 16 + g;
        float* o0 = Out + (size_t)row * D_DIM;
        float* o1 = o0 + (size_t)8 * D_DIM;
#pragma unroll
        for (int ni = 0; ni < 4; ni++) {
            int col = n0 + wn * 32 + ni * 8 + 2 * t;
            float2 bv = *(const float2*)(bias + col);
            float2 v0, v1;
            v0.x = acc[mi][ni][0] + bv.x;  v0.y = acc[mi][ni][1] + bv.y;
            v1.x = acc[mi][ni][2] + bv.x;  v1.y = acc[mi][ni][3] + bv.y;
            *(float2*)(o0 + col) = v0;
            *(float2*)(o1 + col) = v1;
        }
    }
}

// ---------------------------------------------------------------- launch
extern "C" void kernel_launch(void* const* d_in, const int* in_sizes, int n_in,
                              void* d_out, int out_size)
{
    const float* x    = (const float*)d_in[0];  // (4,4096,1024)
    const float* Ws   = (const float*)d_in[3];  // (1024,1024)
    const float* We   = (const float*)d_in[4];  // (1024,1024)
    const float* bias = (const float*)d_in[6];  // (1024,)
    float* out = (float*)d_out;

    cudaFuncSetAttribute(moe_gemm_kernel,
                         cudaFuncAttributeMaxDynamicSharedMemorySize, SMEM_BYTES);

    // fused pre-pass: X -> fp16 (blocks 0..8191), Wc = fp16(Ws+We) (last 512)
    cvt_kernel<<<XBLOCKS + 512, 256>>>(x, Ws, We);

    // GEMM: (16384/128) m-tiles x (1024/128) n-tiles = 1024 CTAs
    moe_gemm_kernel<<<(T_DIM / BM) * (D_DIM / BN), THREADS, SMEM_BYTES>>>(bias, out);
}